// round 4
// baseline (speedup 1.0000x reference)
#include <cuda_runtime.h>

#define NN 50000
#define HD 128
#define EMAX 1700000

// ---------------- f32x2 packed helpers (Blackwell FFMA2 path) --------------
__device__ __forceinline__ unsigned long long pack2(float v) {
    unsigned long long r;
    asm("mov.b64 %0, {%1, %1};" : "=l"(r) : "r"(__float_as_uint(v)));
    return r;
}
__device__ __forceinline__ void fma2(unsigned long long& d,
                                     unsigned long long a,
                                     unsigned long long b) {
    asm("fma.rn.f32x2 %0, %1, %2, %0;" : "+l"(d) : "l"(a), "l"(b));
}
__device__ __forceinline__ float2 unpack2(unsigned long long v) {
    unsigned lo, hi;
    asm("mov.b64 {%0, %1}, %2;" : "=r"(lo), "=r"(hi) : "l"(v));
    return make_float2(__uint_as_float(lo), __uint_as_float(hi));
}

// ---------------- scratch (device globals; no allocation allowed) ----------
__device__ float g_bufA[NN * HD];   // scaled features hs = (X@W)*dinv
__device__ float g_bufB[NN * HD];   // layer activations
__device__ int   g_deg[NN];
__device__ float g_dinv[NN];
__device__ int   g_ptr[NN + 1];
__device__ int   g_cur[NN];
__device__ int   g_srcs[EMAX];

// ---------------- CSR build ------------------------------------------------
__global__ void k_zero_deg() {
    int i = blockIdx.x * blockDim.x + threadIdx.x;
    if (i < NN) g_deg[i] = 0;
}

__global__ void k_hist(const int* __restrict__ ei, int E) {
    int e = blockIdx.x * blockDim.x + threadIdx.x;
    if (e < E) atomicAdd(&g_deg[ei[E + e]], 1);   // dst row of edge_index
}

// single-block exclusive scan over 50000 degrees; also dinv = rsqrt(deg+1)
__global__ void k_scan() {
    __shared__ int s[1024];
    int t = threadIdx.x;
    const int CH = (NN + 1023) / 1024;            // 49
    int st = t * CH;
    int en = min(st + CH, NN);
    int sum = 0;
    for (int i = st; i < en; i++) sum += g_deg[i];
    s[t] = sum;
    __syncthreads();
    for (int off = 1; off < 1024; off <<= 1) {
        int v = (t >= off) ? s[t - off] : 0;
        __syncthreads();
        s[t] += v;
        __syncthreads();
    }
    int base = (t == 0) ? 0 : s[t - 1];
    for (int i = st; i < en; i++) {
        int d = g_deg[i];
        g_ptr[i] = base;
        g_cur[i] = base;
        g_dinv[i] = rsqrtf((float)(d + 1));       // +1 = self loop
        base += d;
    }
    if (t == 1023) g_ptr[NN] = base;
}

__global__ void k_fill(const int* __restrict__ ei, int E) {
    int e = blockIdx.x * blockDim.x + threadIdx.x;
    if (e < E) {
        int d = ei[E + e];
        int pos = atomicAdd(&g_cur[d], 1);
        if (pos < EMAX) g_srcs[pos] = ei[e];
    }
}

// ---------------- GEMM: Out[r] = (X[r] @ W) * dinv[r] ----------------------
// block = 256 threads, 32 rows x 128 cols per block. W in smem; X tile staged
// PRE-DUPLICATED as {x,x} float2 so the inner loop is pure FMA2.
#define GEMM_SMEM (HD * HD * 4 + 32 * HD * 8)

__global__ __launch_bounds__(256) void k_gemm_scale(
    const float* __restrict__ X, const float* __restrict__ W,
    float* __restrict__ Out)
{
    extern __shared__ float sm[];
    float* sW = sm;                                          // 128x128 (64KB)
    unsigned long long* sXd = (unsigned long long*)(sm + HD * HD); // 32x128 dup (32KB)
    int tid = threadIdx.x;

    float4* sW4 = (float4*)sW;
    const float4* W4 = (const float4*)W;
    for (int i = tid; i < HD * HD / 4; i += 256) sW4[i] = W4[i];

    int row0 = blockIdx.x * 32;
    int nr = min(32, NN - row0);
    const float4* X4 = (const float4*)(X + (size_t)row0 * HD);
    for (int i = tid; i < nr * (HD / 4); i += 256) {
        float4 v = X4[i];
        int row = i >> 5;          // /32 float4s per row
        int j = i & 31;
        int base = row * HD + j * 4;
        sXd[base + 0] = pack2(v.x);
        sXd[base + 1] = pack2(v.y);
        sXd[base + 2] = pack2(v.z);
        sXd[base + 3] = pack2(v.w);
    }
    __syncthreads();

    int tx = tid & 31;              // col group: cols tx*4 .. tx*4+3
    int ty = tid >> 5;              // 0..7 ; rows ty, ty+8, ty+16, ty+24
    unsigned long long acc[4][2];
#pragma unroll
    for (int r = 0; r < 4; r++) { acc[r][0] = 0ull; acc[r][1] = 0ull; }

    const ulonglong2* sW2 = (const ulonglong2*)sW;
#pragma unroll 4
    for (int k = 0; k < HD; k++) {
        ulonglong2 w = sW2[k * 32 + tx];        // cols tx*4..tx*4+3 packed
#pragma unroll
        for (int r = 0; r < 4; r++) {
            unsigned long long cc = sXd[(ty + r * 8) * HD + k]; // broadcast
            fma2(acc[r][0], cc, w.x);
            fma2(acc[r][1], cc, w.y);
        }
    }

#pragma unroll
    for (int r = 0; r < 4; r++) {
        int row = ty + r * 8;
        if (row < nr) {
            int grow = row0 + row;
            float di = g_dinv[grow];
            float2 lo = unpack2(acc[r][0]);
            float2 hi = unpack2(acc[r][1]);
            float4 v = make_float4(lo.x * di, lo.y * di, hi.x * di, hi.y * di);
            ((float4*)(Out + (size_t)grow * HD))[tx] = v;
        }
    }
}

// ---------------- SpMM: warp per dst node, pull-based, no atomics ----------
// Out[d] = relu( dinv[d] * (HS[d] + sum_{src in N(d)} HS[src]) + bias )
__global__ __launch_bounds__(256) void k_spmm(
    const float* __restrict__ HS, const float* __restrict__ bias,
    float* __restrict__ Out)
{
    int gw = (blockIdx.x * blockDim.x + threadIdx.x) >> 5;
    int lane = threadIdx.x & 31;
    if (gw >= NN) return;

    const float4* hs4 = (const float4*)HS;
    float4 acc = hs4[(size_t)gw * 32 + lane];       // self-loop term
    int p0 = g_ptr[gw], p1 = g_ptr[gw + 1];

    int e = p0;
    for (; e + 32 <= p1; e += 32) {
        int idx = g_srcs[e + lane];
#pragma unroll
        for (int j = 0; j < 32; j++) {
            int s = __shfl_sync(0xffffffffu, idx, j);
            float4 v = hs4[(size_t)s * 32 + lane];
            acc.x += v.x; acc.y += v.y; acc.z += v.z; acc.w += v.w;
        }
    }
    if (e < p1) {
        int m = p1 - e;
        int idx = (lane < m) ? g_srcs[e + lane] : 0;
        for (int j = 0; j < m; j++) {
            int s = __shfl_sync(0xffffffffu, idx, j);
            float4 v = hs4[(size_t)s * 32 + lane];
            acc.x += v.x; acc.y += v.y; acc.z += v.z; acc.w += v.w;
        }
    }

    float di = g_dinv[gw];
    float4 b = ((const float4*)bias)[lane];
    float4 o;
    o.x = fmaxf(fmaf(acc.x, di, b.x), 0.f);
    o.y = fmaxf(fmaf(acc.y, di, b.y), 0.f);
    o.z = fmaxf(fmaf(acc.z, di, b.z), 0.f);
    o.w = fmaxf(fmaf(acc.w, di, b.w), 0.f);
    ((float4*)Out)[(size_t)gw * 32 + lane] = o;
}

// ---------------- pair MLP (FMA2 version) ----------------------------------
// out[p] = relu([h[p0], h[p1]] @ Wh1 + bh1) @ Wh2 + bh2
// Wh1 (256x128 f32 = 128KB) in dynamic smem. Warp processes 4 pairs sharing
// every W load. Lane owns output cols lane*4..lane*4+3, packed as 2x f32x2.
#define MLP_SMEM ((256 * HD + HD + HD) * 4)
#define MLP_PAIRS 4

__global__ __launch_bounds__(512) void k_mlp(
    const float* __restrict__ H2, const int* __restrict__ pairs,
    const float* __restrict__ Wh1, const float* __restrict__ bh1,
    const float* __restrict__ Wh2, const float* __restrict__ bh2,
    float* __restrict__ out, int P)
{
    extern __shared__ float sm[];
    float* sW = sm;                  // 256*128
    float* sb = sm + 256 * HD;       // 128
    float* sw2 = sb + HD;            // 128
    int tid = threadIdx.x;

    const float4* W4 = (const float4*)Wh1;
    float4* sW4 = (float4*)sW;
    for (int i = tid; i < 256 * HD / 4; i += blockDim.x) sW4[i] = W4[i];
    if (tid < HD) { sb[tid] = bh1[tid]; sw2[tid] = Wh2[tid]; }
    __syncthreads();

    int lane = tid & 31;
    int wid = (blockIdx.x * blockDim.x + tid) >> 5;
    int nwarps = (gridDim.x * blockDim.x) >> 5;
    float bias2 = bh2[0];
    const float4* h4 = (const float4*)H2;
    const ulonglong2* sW2p = (const ulonglong2*)sW;

    for (int pb = wid * MLP_PAIRS; pb < P; pb += nwarps * MLP_PAIRS) {
        int pi[MLP_PAIRS];
        float a[MLP_PAIRS][4], b[MLP_PAIRS][4];
        unsigned long long z[MLP_PAIRS][2];
#pragma unroll
        for (int q = 0; q < MLP_PAIRS; q++) {
            pi[q] = min(pb + q, P - 1);
            int n0 = pairs[2 * pi[q]];
            int n1 = pairs[2 * pi[q] + 1];
            float4 av = h4[(size_t)n0 * 32 + lane];
            float4 bv = h4[(size_t)n1 * 32 + lane];
            a[q][0] = av.x; a[q][1] = av.y; a[q][2] = av.z; a[q][3] = av.w;
            b[q][0] = bv.x; b[q][1] = bv.y; b[q][2] = bv.z; b[q][3] = bv.w;
            z[q][0] = 0ull; z[q][1] = 0ull;
        }

        // first half: k in [0,128), operand = h[p0]
#pragma unroll 2
        for (int sl = 0; sl < 32; sl++) {
#pragma unroll
            for (int qq = 0; qq < 4; qq++) {
                int k = sl * 4 + qq;
                ulonglong2 w = sW2p[k * 32 + lane];
#pragma unroll
                for (int q = 0; q < MLP_PAIRS; q++) {
                    float c = __shfl_sync(0xffffffffu, a[q][qq], sl);
                    unsigned long long cc = pack2(c);
                    fma2(z[q][0], cc, w.x);
                    fma2(z[q][1], cc, w.y);
                }
            }
        }
        // second half: k in [128,256), operand = h[p1]
#pragma unroll 2
        for (int sl = 0; sl < 32; sl++) {
#pragma unroll
            for (int qq = 0; qq < 4; qq++) {
                int k = 128 + sl * 4 + qq;
                ulonglong2 w = sW2p[k * 32 + lane];
#pragma unroll
                for (int q = 0; q < MLP_PAIRS; q++) {
                    float c = __shfl_sync(0xffffffffu, b[q][qq], sl);
                    unsigned long long cc = pack2(c);
                    fma2(z[q][0], cc, w.x);
                    fma2(z[q][1], cc, w.y);
                }
            }
        }

        float4 b1v = ((const float4*)sb)[lane];
        float4 w2v = ((const float4*)sw2)[lane];
#pragma unroll
        for (int q = 0; q < MLP_PAIRS; q++) {
            float2 zlo = unpack2(z[q][0]);
            float2 zhi = unpack2(z[q][1]);
            float s =
                fmaxf(zlo.x + b1v.x, 0.f) * w2v.x +
                fmaxf(zlo.y + b1v.y, 0.f) * w2v.y +
                fmaxf(zhi.x + b1v.z, 0.f) * w2v.z +
                fmaxf(zhi.y + b1v.w, 0.f) * w2v.w;
#pragma unroll
            for (int o = 16; o > 0; o >>= 1)
                s += __shfl_xor_sync(0xffffffffu, s, o);
            if (lane == 0 && pb + q < P) out[pi[q]] = s + bias2;
        }
    }
}

// ---------------- launch ---------------------------------------------------
extern "C" void kernel_launch(void* const* d_in, const int* in_sizes, int n_in,
                              void* d_out, int out_size)
{
    const float* x    = (const float*)d_in[0];
    const int*   ei   = (const int*)d_in[1];
    const int*   prs  = (const int*)d_in[2];
    const float* W1   = (const float*)d_in[3];
    const float* b1   = (const float*)d_in[4];
    const float* W2   = (const float*)d_in[5];
    const float* b2   = (const float*)d_in[6];
    const float* Wh1  = (const float*)d_in[7];
    const float* bh1  = (const float*)d_in[8];
    const float* Wh2  = (const float*)d_in[9];
    const float* bh2  = (const float*)d_in[10];
    float* out = (float*)d_out;

    int E = in_sizes[1] / 2;
    int P = in_sizes[2] / 2;

    cudaFuncSetAttribute(k_gemm_scale,
                         cudaFuncAttributeMaxDynamicSharedMemorySize, GEMM_SMEM);
    cudaFuncSetAttribute(k_mlp,
                         cudaFuncAttributeMaxDynamicSharedMemorySize, MLP_SMEM);

    void *pA = nullptr, *pB = nullptr;
    cudaGetSymbolAddress(&pA, g_bufA);
    cudaGetSymbolAddress(&pB, g_bufB);
    float* A = (float*)pA;
    float* B = (float*)pB;

    // CSR build (once per launch; same adjacency for both layers)
    k_zero_deg<<<(NN + 255) / 256, 256>>>();
    k_hist<<<(E + 255) / 256, 256>>>(ei, E);
    k_scan<<<1, 1024>>>();
    k_fill<<<(E + 255) / 256, 256>>>(ei, E);

    // layer 1
    k_gemm_scale<<<(NN + 31) / 32, 256, GEMM_SMEM>>>(x, W1, A);
    k_spmm<<<(NN * 32 + 255) / 256, 256>>>(A, b1, B);
    // layer 2
    k_gemm_scale<<<(NN + 31) / 32, 256, GEMM_SMEM>>>(B, W2, A);
    k_spmm<<<(NN * 32 + 255) / 256, 256>>>(A, b2, B);
    // pair MLP head
    k_mlp<<<148, 512, MLP_SMEM>>>(B, prs, Wh1, bh1, Wh2, bh2, out, P);
}

// round 5
// speedup vs baseline: 1.5305x; 1.5305x over previous
#include <cuda_runtime.h>

#define NN 50000
#define HD 128
#define EMAX 1700000

// ---------------- scratch (device globals; no allocation allowed) ----------
__device__ float g_bufA[NN * HD];   // scaled features hs = (X@W)*dinv
__device__ float g_bufB[NN * HD];   // layer activations
__device__ float g_bufU[NN * HD];   // U = h2 @ Wh1_top
__device__ float g_bufV[NN * HD];   // V = h2 @ Wh1_bot
__device__ int   g_deg[NN];
__device__ float g_dinv[NN];
__device__ int   g_ptr[NN + 1];
__device__ int   g_cur[NN];
__device__ int   g_srcs[EMAX];

// ---------------- CSR build ------------------------------------------------
__global__ void k_zero_deg() {
    int i = blockIdx.x * blockDim.x + threadIdx.x;
    if (i < NN) g_deg[i] = 0;
}

__global__ void k_hist(const int* __restrict__ ei, int E) {
    int e = blockIdx.x * blockDim.x + threadIdx.x;
    if (e < E) atomicAdd(&g_deg[ei[E + e]], 1);   // dst row of edge_index
}

// single-block exclusive scan over 50000 degrees; also dinv = rsqrt(deg+1)
__global__ void k_scan() {
    __shared__ int s[1024];
    int t = threadIdx.x;
    const int CH = (NN + 1023) / 1024;            // 49
    int st = t * CH;
    int en = min(st + CH, NN);
    int sum = 0;
    for (int i = st; i < en; i++) sum += g_deg[i];
    s[t] = sum;
    __syncthreads();
    for (int off = 1; off < 1024; off <<= 1) {
        int v = (t >= off) ? s[t - off] : 0;
        __syncthreads();
        s[t] += v;
        __syncthreads();
    }
    int base = (t == 0) ? 0 : s[t - 1];
    for (int i = st; i < en; i++) {
        int d = g_deg[i];
        g_ptr[i] = base;
        g_cur[i] = base;
        g_dinv[i] = rsqrtf((float)(d + 1));       // +1 = self loop
        base += d;
    }
    if (t == 1023) g_ptr[NN] = base;
}

__global__ void k_fill(const int* __restrict__ ei, int E) {
    int e = blockIdx.x * blockDim.x + threadIdx.x;
    if (e < E) {
        int d = ei[E + e];
        int pos = atomicAdd(&g_cur[d], 1);
        if (pos < EMAX) g_srcs[pos] = ei[e];
    }
}

// ---------------- GEMM: Out[r] = (X[r] @ W) [* dinv[r] if SCALE] -----------
// block = 256 threads, 32 rows x 128 cols per block. W fully in smem.
#define GEMM_SMEM ((HD * HD + 32 * HD) * 4)

template <bool SCALE>
__global__ __launch_bounds__(256) void k_gemm(
    const float* __restrict__ X, const float* __restrict__ W,
    float* __restrict__ Out)
{
    extern __shared__ float sm[];
    float* sW = sm;                 // 128x128
    float* sX = sm + HD * HD;       // 32x128
    int tid = threadIdx.x;

    float4* sW4 = (float4*)sW;
    const float4* W4 = (const float4*)W;
    for (int i = tid; i < HD * HD / 4; i += 256) sW4[i] = W4[i];

    int row0 = blockIdx.x * 32;
    int nr = min(32, NN - row0);
    const float4* X4 = (const float4*)(X + (size_t)row0 * HD);
    float4* sX4 = (float4*)sX;
    for (int i = tid; i < nr * (HD / 4); i += 256) sX4[i] = X4[i];
    __syncthreads();

    int tx = tid & 31;              // col group: cols tx*4 .. tx*4+3
    int ty = tid >> 5;              // 0..7 ; rows ty, ty+8, ty+16, ty+24
    float4 acc[4];
    acc[0] = acc[1] = acc[2] = acc[3] = make_float4(0.f, 0.f, 0.f, 0.f);

#pragma unroll 4
    for (int k = 0; k < HD; k++) {
        float4 w = sW4[k * (HD / 4) + tx];
#pragma unroll
        for (int r = 0; r < 4; r++) {
            float xv = sX[(ty + r * 8) * HD + k];   // warp-uniform broadcast
            acc[r].x += xv * w.x;
            acc[r].y += xv * w.y;
            acc[r].z += xv * w.z;
            acc[r].w += xv * w.w;
        }
    }

#pragma unroll
    for (int r = 0; r < 4; r++) {
        int row = ty + r * 8;
        if (row < nr) {
            int grow = row0 + row;
            float s = SCALE ? g_dinv[grow] : 1.0f;
            float4 v = make_float4(acc[r].x * s, acc[r].y * s,
                                   acc[r].z * s, acc[r].w * s);
            ((float4*)(Out + (size_t)grow * HD))[tx] = v;
        }
    }
}

// ---------------- SpMM: warp per dst node, pull-based, no atomics ----------
// Out[d] = relu( dinv[d] * (HS[d] + sum_{src in N(d)} HS[src]) + bias )
__global__ __launch_bounds__(256) void k_spmm(
    const float* __restrict__ HS, const float* __restrict__ bias,
    float* __restrict__ Out)
{
    int gw = (blockIdx.x * blockDim.x + threadIdx.x) >> 5;
    int lane = threadIdx.x & 31;
    if (gw >= NN) return;

    const float4* hs4 = (const float4*)HS;
    float4 acc = hs4[(size_t)gw * 32 + lane];       // self-loop term
    int p0 = g_ptr[gw], p1 = g_ptr[gw + 1];

    int e = p0;
    for (; e + 32 <= p1; e += 32) {
        int idx = g_srcs[e + lane];
#pragma unroll
        for (int j = 0; j < 32; j++) {
            int s = __shfl_sync(0xffffffffu, idx, j);
            float4 v = hs4[(size_t)s * 32 + lane];
            acc.x += v.x; acc.y += v.y; acc.z += v.z; acc.w += v.w;
        }
    }
    if (e < p1) {
        int m = p1 - e;
        int idx = (lane < m) ? g_srcs[e + lane] : 0;
        for (int j = 0; j < m; j++) {
            int s = __shfl_sync(0xffffffffu, idx, j);
            float4 v = hs4[(size_t)s * 32 + lane];
            acc.x += v.x; acc.y += v.y; acc.z += v.z; acc.w += v.w;
        }
    }

    float di = g_dinv[gw];
    float4 b = ((const float4*)bias)[lane];
    float4 o;
    o.x = fmaxf(fmaf(acc.x, di, b.x), 0.f);
    o.y = fmaxf(fmaf(acc.y, di, b.y), 0.f);
    o.z = fmaxf(fmaf(acc.z, di, b.z), 0.f);
    o.w = fmaxf(fmaf(acc.w, di, b.w), 0.f);
    ((float4*)Out)[(size_t)gw * 32 + lane] = o;
}

// ---------------- pair epilogue --------------------------------------------
// out[p] = relu(U[p0] + V[p1] + bh1) . Wh2 + bh2
// One warp per pair; lane owns 4 of the 128 hidden dims.
__global__ __launch_bounds__(256) void k_pair(
    const int* __restrict__ pairs,
    const float* __restrict__ bh1, const float* __restrict__ Wh2,
    const float* __restrict__ bh2,
    float* __restrict__ out, int P)
{
    int gw = (blockIdx.x * blockDim.x + threadIdx.x) >> 5;
    int lane = threadIdx.x & 31;
    if (gw >= P) return;

    int n0 = pairs[2 * gw];
    int n1 = pairs[2 * gw + 1];

    const float4* U4 = (const float4*)g_bufU;
    const float4* V4 = (const float4*)g_bufV;
    float4 u = U4[(size_t)n0 * 32 + lane];
    float4 v = V4[(size_t)n1 * 32 + lane];
    float4 b = ((const float4*)bh1)[lane];
    float4 w = ((const float4*)Wh2)[lane];

    float s = fmaxf(u.x + v.x + b.x, 0.f) * w.x
            + fmaxf(u.y + v.y + b.y, 0.f) * w.y
            + fmaxf(u.z + v.z + b.z, 0.f) * w.z
            + fmaxf(u.w + v.w + b.w, 0.f) * w.w;
#pragma unroll
    for (int o = 16; o > 0; o >>= 1)
        s += __shfl_xor_sync(0xffffffffu, s, o);
    if (lane == 0) out[gw] = s + bh2[0];
}

// ---------------- launch ---------------------------------------------------
extern "C" void kernel_launch(void* const* d_in, const int* in_sizes, int n_in,
                              void* d_out, int out_size)
{
    const float* x    = (const float*)d_in[0];
    const int*   ei   = (const int*)d_in[1];
    const int*   prs  = (const int*)d_in[2];
    const float* W1   = (const float*)d_in[3];
    const float* b1   = (const float*)d_in[4];
    const float* W2   = (const float*)d_in[5];
    const float* b2   = (const float*)d_in[6];
    const float* Wh1  = (const float*)d_in[7];
    const float* bh1  = (const float*)d_in[8];
    const float* Wh2  = (const float*)d_in[9];
    const float* bh2  = (const float*)d_in[10];
    float* out = (float*)d_out;

    int E = in_sizes[1] / 2;
    int P = in_sizes[2] / 2;

    cudaFuncSetAttribute(k_gemm<true>,
                         cudaFuncAttributeMaxDynamicSharedMemorySize, GEMM_SMEM);
    cudaFuncSetAttribute(k_gemm<false>,
                         cudaFuncAttributeMaxDynamicSharedMemorySize, GEMM_SMEM);

    void *pA = nullptr, *pB = nullptr, *pU = nullptr, *pV = nullptr;
    cudaGetSymbolAddress(&pA, g_bufA);
    cudaGetSymbolAddress(&pB, g_bufB);
    cudaGetSymbolAddress(&pU, g_bufU);
    cudaGetSymbolAddress(&pV, g_bufV);
    float* A = (float*)pA;
    float* B = (float*)pB;
    float* U = (float*)pU;
    float* V = (float*)pV;

    // CSR build (once per launch; same adjacency for both layers)
    k_zero_deg<<<(NN + 255) / 256, 256>>>();
    k_hist<<<(E + 255) / 256, 256>>>(ei, E);
    k_scan<<<1, 1024>>>();
    k_fill<<<(E + 255) / 256, 256>>>(ei, E);

    const int GB = (NN + 31) / 32;
    // layer 1
    k_gemm<true><<<GB, 256, GEMM_SMEM>>>(x, W1, A);
    k_spmm<<<(NN * 32 + 255) / 256, 256>>>(A, b1, B);
    // layer 2
    k_gemm<true><<<GB, 256, GEMM_SMEM>>>(B, W2, A);
    k_spmm<<<(NN * 32 + 255) / 256, 256>>>(A, b2, B);
    // factored pair-MLP: U = h2 @ Wh1_top, V = h2 @ Wh1_bot
    k_gemm<false><<<GB, 256, GEMM_SMEM>>>(B, Wh1, U);
    k_gemm<false><<<GB, 256, GEMM_SMEM>>>(B, Wh1 + HD * HD, V);
    // pair epilogue
    k_pair<<<(P * 32 + 255) / 256, 256>>>(prs, bh1, Wh2, bh2, out, P);
}

// round 6
// speedup vs baseline: 1.5430x; 1.0081x over previous
#include <cuda_runtime.h>

#define NN 50000
#define HD 128
#define EMAX 1700000

// ---------------- scratch (device globals; no allocation allowed) ----------
__device__ float g_bufA[NN * HD];   // pre-aggregation features
__device__ float g_bufB[NN * HD];   // layer activations
__device__ float g_bufU[NN * HD];   // U = h2 @ Wh1_top
__device__ float g_bufV[NN * HD];   // V = h2 @ Wh1_bot
__device__ int   g_deg[NN];
__device__ float g_dinv[NN];
__device__ int   g_ptr[NN + 1];
__device__ int   g_cur[NN];
__device__ int   g_srcs[EMAX];

// ---------------- CSR build ------------------------------------------------
__global__ void k_zero_deg() {
    int i = blockIdx.x * blockDim.x + threadIdx.x;
    if (i < NN) g_deg[i] = 0;
}

__global__ void k_hist(const int* __restrict__ ei, int E) {
    int e = blockIdx.x * blockDim.x + threadIdx.x;
    if (e < E) atomicAdd(&g_deg[ei[E + e]], 1);   // dst row of edge_index
}

// single-block exclusive scan over 50000 degrees; also dinv = rsqrt(deg+1)
__global__ void k_scan() {
    __shared__ int s[1024];
    int t = threadIdx.x;
    const int CH = (NN + 1023) / 1024;            // 49
    int st = t * CH;
    int en = min(st + CH, NN);
    int sum = 0;
    for (int i = st; i < en; i++) sum += g_deg[i];
    s[t] = sum;
    __syncthreads();
    for (int off = 1; off < 1024; off <<= 1) {
        int v = (t >= off) ? s[t - off] : 0;
        __syncthreads();
        s[t] += v;
        __syncthreads();
    }
    int base = (t == 0) ? 0 : s[t - 1];
    for (int i = st; i < en; i++) {
        int d = g_deg[i];
        g_ptr[i] = base;
        g_cur[i] = base;
        g_dinv[i] = rsqrtf((float)(d + 1));       // +1 = self loop
        base += d;
    }
    if (t == 1023) g_ptr[NN] = base;
}

__global__ void k_fill(const int* __restrict__ ei, int E) {
    int e = blockIdx.x * blockDim.x + threadIdx.x;
    if (e < E) {
        int d = ei[E + e];
        int pos = atomicAdd(&g_cur[d], 1);
        if (pos < EMAX) g_srcs[pos] = ei[e];
    }
}

// ---------------- GEMM: Out[r] = (X[r] @ W) [* dinv[r] if SCALE] -----------
// block = 256 threads, 32 rows x 128 cols per block. W fully in smem.
#define GEMM_SMEM ((HD * HD + 32 * HD) * 4)

template <bool SCALE>
__global__ __launch_bounds__(256) void k_gemm(
    const float* __restrict__ X, const float* __restrict__ W,
    float* __restrict__ Out)
{
    extern __shared__ float sm[];
    float* sW = sm;                 // 128x128
    float* sX = sm + HD * HD;       // 32x128
    int tid = threadIdx.x;

    float4* sW4 = (float4*)sW;
    const float4* W4 = (const float4*)W;
    for (int i = tid; i < HD * HD / 4; i += 256) sW4[i] = W4[i];

    int row0 = blockIdx.x * 32;
    int nr = min(32, NN - row0);
    const float4* X4 = (const float4*)(X + (size_t)row0 * HD);
    float4* sX4 = (float4*)sX;
    for (int i = tid; i < nr * (HD / 4); i += 256) sX4[i] = X4[i];
    __syncthreads();

    int tx = tid & 31;              // col group: cols tx*4 .. tx*4+3
    int ty = tid >> 5;              // 0..7 ; rows ty, ty+8, ty+16, ty+24
    float4 acc[4];
    acc[0] = acc[1] = acc[2] = acc[3] = make_float4(0.f, 0.f, 0.f, 0.f);

#pragma unroll 4
    for (int k = 0; k < HD; k++) {
        float4 w = sW4[k * (HD / 4) + tx];
#pragma unroll
        for (int r = 0; r < 4; r++) {
            float xv = sX[(ty + r * 8) * HD + k];   // warp-uniform broadcast
            acc[r].x += xv * w.x;
            acc[r].y += xv * w.y;
            acc[r].z += xv * w.z;
            acc[r].w += xv * w.w;
        }
    }

#pragma unroll
    for (int r = 0; r < 4; r++) {
        int row = ty + r * 8;
        if (row < nr) {
            int grow = row0 + row;
            float s = SCALE ? g_dinv[grow] : 1.0f;
            float4 v = make_float4(acc[r].x * s, acc[r].y * s,
                                   acc[r].z * s, acc[r].w * s);
            ((float4*)(Out + (size_t)grow * HD))[tx] = v;
        }
    }
}

// ---------------- merged U/V GEMM: blockIdx.y picks Wh1 half ---------------
__global__ __launch_bounds__(256) void k_gemm_uv(
    const float* __restrict__ X, const float* __restrict__ Wh1,
    float* __restrict__ U, float* __restrict__ V)
{
    extern __shared__ float sm[];
    float* sW = sm;
    float* sX = sm + HD * HD;
    int tid = threadIdx.x;
    const float* W = Wh1 + (size_t)blockIdx.y * HD * HD;
    float* Out = blockIdx.y ? V : U;

    float4* sW4 = (float4*)sW;
    const float4* W4 = (const float4*)W;
    for (int i = tid; i < HD * HD / 4; i += 256) sW4[i] = W4[i];

    int row0 = blockIdx.x * 32;
    int nr = min(32, NN - row0);
    const float4* X4 = (const float4*)(X + (size_t)row0 * HD);
    float4* sX4 = (float4*)sX;
    for (int i = tid; i < nr * (HD / 4); i += 256) sX4[i] = X4[i];
    __syncthreads();

    int tx = tid & 31;
    int ty = tid >> 5;
    float4 acc[4];
    acc[0] = acc[1] = acc[2] = acc[3] = make_float4(0.f, 0.f, 0.f, 0.f);

#pragma unroll 4
    for (int k = 0; k < HD; k++) {
        float4 w = sW4[k * (HD / 4) + tx];
#pragma unroll
        for (int r = 0; r < 4; r++) {
            float xv = sX[(ty + r * 8) * HD + k];
            acc[r].x += xv * w.x;
            acc[r].y += xv * w.y;
            acc[r].z += xv * w.z;
            acc[r].w += xv * w.w;
        }
    }

#pragma unroll
    for (int r = 0; r < 4; r++) {
        int row = ty + r * 8;
        if (row < nr) {
            int grow = row0 + row;
            ((float4*)(Out + (size_t)grow * HD))[tx] = acc[r];
        }
    }
}

// ---------------- SpMM: warp per dst node, pull-based, no atomics ----------
// SRCSCALE=true : HS is raw X@W; gathered rows scaled by dinv[src] on the fly.
// SRCSCALE=false: HS already scaled by dinv (GEMM epilogue).
// Out[d] = relu( dinv[d] * (self + sum) + bias )
template <bool SRCSCALE>
__global__ __launch_bounds__(256) void k_spmm(
    const float* __restrict__ HS, const float* __restrict__ bias,
    float* __restrict__ Out)
{
    int gw = (blockIdx.x * blockDim.x + threadIdx.x) >> 5;
    int lane = threadIdx.x & 31;
    if (gw >= NN) return;

    float di = g_dinv[gw];
    const float4* hs4 = (const float4*)HS;
    float4 self = hs4[(size_t)gw * 32 + lane];
    float4 acc;
    if (SRCSCALE) {
        acc.x = self.x * di; acc.y = self.y * di;
        acc.z = self.z * di; acc.w = self.w * di;
    } else {
        acc = self;
    }
    int p0 = g_ptr[gw], p1 = g_ptr[gw + 1];

    int e = p0;
    for (; e + 32 <= p1; e += 32) {
        int idx = g_srcs[e + lane];
        float dv = SRCSCALE ? g_dinv[idx] : 0.f;
#pragma unroll
        for (int j = 0; j < 32; j++) {
            int s = __shfl_sync(0xffffffffu, idx, j);
            float4 v = hs4[(size_t)s * 32 + lane];
            if (SRCSCALE) {
                float ds = __shfl_sync(0xffffffffu, dv, j);
                acc.x = fmaf(v.x, ds, acc.x);
                acc.y = fmaf(v.y, ds, acc.y);
                acc.z = fmaf(v.z, ds, acc.z);
                acc.w = fmaf(v.w, ds, acc.w);
            } else {
                acc.x += v.x; acc.y += v.y; acc.z += v.z; acc.w += v.w;
            }
        }
    }
    if (e < p1) {
        int m = p1 - e;
        int idx = (lane < m) ? g_srcs[e + lane] : 0;
        float dv = SRCSCALE ? ((lane < m) ? g_dinv[idx] : 0.f) : 0.f;
        for (int j = 0; j < m; j++) {
            int s = __shfl_sync(0xffffffffu, idx, j);
            float4 v = hs4[(size_t)s * 32 + lane];
            if (SRCSCALE) {
                float ds = __shfl_sync(0xffffffffu, dv, j);
                acc.x = fmaf(v.x, ds, acc.x);
                acc.y = fmaf(v.y, ds, acc.y);
                acc.z = fmaf(v.z, ds, acc.z);
                acc.w = fmaf(v.w, ds, acc.w);
            } else {
                acc.x += v.x; acc.y += v.y; acc.z += v.z; acc.w += v.w;
            }
        }
    }

    float4 b = ((const float4*)bias)[lane];
    float4 o;
    o.x = fmaxf(fmaf(acc.x, di, b.x), 0.f);
    o.y = fmaxf(fmaf(acc.y, di, b.y), 0.f);
    o.z = fmaxf(fmaf(acc.z, di, b.z), 0.f);
    o.w = fmaxf(fmaf(acc.w, di, b.w), 0.f);
    ((float4*)Out)[(size_t)gw * 32 + lane] = o;
}

// ---------------- pair epilogue --------------------------------------------
// out[p] = relu(U[p0] + V[p1] + bh1) . Wh2 + bh2
__global__ __launch_bounds__(256) void k_pair(
    const int* __restrict__ pairs,
    const float* __restrict__ bh1, const float* __restrict__ Wh2,
    const float* __restrict__ bh2,
    float* __restrict__ out, int P)
{
    int gw = (blockIdx.x * blockDim.x + threadIdx.x) >> 5;
    int lane = threadIdx.x & 31;
    if (gw >= P) return;

    int n0 = pairs[2 * gw];
    int n1 = pairs[2 * gw + 1];

    const float4* U4 = (const float4*)g_bufU;
    const float4* V4 = (const float4*)g_bufV;
    float4 u = U4[(size_t)n0 * 32 + lane];
    float4 v = V4[(size_t)n1 * 32 + lane];
    float4 b = ((const float4*)bh1)[lane];
    float4 w = ((const float4*)Wh2)[lane];

    float s = fmaxf(u.x + v.x + b.x, 0.f) * w.x
            + fmaxf(u.y + v.y + b.y, 0.f) * w.y
            + fmaxf(u.z + v.z + b.z, 0.f) * w.z
            + fmaxf(u.w + v.w + b.w, 0.f) * w.w;
#pragma unroll
    for (int o = 16; o > 0; o >>= 1)
        s += __shfl_xor_sync(0xffffffffu, s, o);
    if (lane == 0) out[gw] = s + bh2[0];
}

// ---------------- launch ---------------------------------------------------
extern "C" void kernel_launch(void* const* d_in, const int* in_sizes, int n_in,
                              void* d_out, int out_size)
{
    const float* x    = (const float*)d_in[0];
    const int*   ei   = (const int*)d_in[1];
    const int*   prs  = (const int*)d_in[2];
    const float* W1   = (const float*)d_in[3];
    const float* b1   = (const float*)d_in[4];
    const float* W2   = (const float*)d_in[5];
    const float* b2   = (const float*)d_in[6];
    const float* Wh1  = (const float*)d_in[7];
    const float* bh1  = (const float*)d_in[8];
    const float* Wh2  = (const float*)d_in[9];
    const float* bh2  = (const float*)d_in[10];
    float* out = (float*)d_out;

    int E = in_sizes[1] / 2;
    int P = in_sizes[2] / 2;

    // one-time host objects (no device memory involved)
    static cudaStream_t s2 = []() {
        cudaStream_t s;
        cudaStreamCreateWithFlags(&s, cudaStreamNonBlocking);
        return s;
    }();
    static cudaEvent_t evFork = []() {
        cudaEvent_t e;
        cudaEventCreateWithFlags(&e, cudaEventDisableTiming);
        return e;
    }();
    static cudaEvent_t evJoin = []() {
        cudaEvent_t e;
        cudaEventCreateWithFlags(&e, cudaEventDisableTiming);
        return e;
    }();

    cudaFuncSetAttribute(k_gemm<true>,
                         cudaFuncAttributeMaxDynamicSharedMemorySize, GEMM_SMEM);
    cudaFuncSetAttribute(k_gemm<false>,
                         cudaFuncAttributeMaxDynamicSharedMemorySize, GEMM_SMEM);
    cudaFuncSetAttribute(k_gemm_uv,
                         cudaFuncAttributeMaxDynamicSharedMemorySize, GEMM_SMEM);

    void *pA = nullptr, *pB = nullptr, *pU = nullptr, *pV = nullptr;
    cudaGetSymbolAddress(&pA, g_bufA);
    cudaGetSymbolAddress(&pB, g_bufB);
    cudaGetSymbolAddress(&pU, g_bufU);
    cudaGetSymbolAddress(&pV, g_bufV);
    float* A = (float*)pA;
    float* B = (float*)pB;
    float* U = (float*)pU;
    float* V = (float*)pV;

    const int GB = (NN + 31) / 32;

    // fork: CSR build chain on s2, concurrent with GEMM1 on main stream
    cudaEventRecord(evFork, 0);
    cudaStreamWaitEvent(s2, evFork, 0);

    k_zero_deg<<<(NN + 255) / 256, 256, 0, s2>>>();
    k_hist<<<(E + 255) / 256, 256, 0, s2>>>(ei, E);
    k_scan<<<1, 1024, 0, s2>>>();
    k_fill<<<(E + 255) / 256, 256, 0, s2>>>(ei, E);

    // GEMM1 (raw X@W1 — no dinv dependency, overlaps CSR build)
    k_gemm<false><<<GB, 256, GEMM_SMEM>>>(x, W1, A);

    // join
    cudaEventRecord(evJoin, s2);
    cudaStreamWaitEvent(0, evJoin, 0);

    // layer 1 aggregation: dinv[src] applied at gather time
    k_spmm<true><<<(NN * 32 + 255) / 256, 256>>>(A, b1, B);
    // layer 2
    k_gemm<true><<<GB, 256, GEMM_SMEM>>>(B, W2, A);
    k_spmm<false><<<(NN * 32 + 255) / 256, 256>>>(A, b2, B);
    // factored pair-MLP head: U and V in one launch
    dim3 guv(GB, 2);
    k_gemm_uv<<<guv, 256, GEMM_SMEM>>>(B, Wh1, U, V);
    // pair epilogue
    k_pair<<<(P * 32 + 255) / 256, 256>>>(prs, bh1, Wh2, bh2, out, P);
}